// round 2
// baseline (speedup 1.0000x reference)
#include <cuda_runtime.h>

#define D    4096
#define TPB  256
#define VPT  16            // values per thread per row (4 x float4)
#define NWARP (TPB / 32)

__device__ __forceinline__ float4 ldcs4(const float4* p) {
    return __ldcs(p);
}

// 50-step bisection identical (fp32 op-for-op) to the reference trajectory.
// mask = (sum(Z)-1 >= 0). p = 1/4095 => u^p in [0.975,1] for every positive
// fp32 u, so mask <=> count(Xs_j > t) >= 2, except count==1 where
// sum = powf(u1,p) which can round to >= 1.0f only when u1 is extremely
// close to 1 (guard 0.999f, then evaluate the same libdevice powf).
__device__ __forceinline__ float bisect_t(float H, float L) {
    const float p = (float)(1.0 / 4095.0);
    float t_min = H - 1.0f;          // m - 1
    float t_max = H - 0.015625f;     // m - 4096^(1-1.5)
    float diff  = t_max - t_min;
    float t     = t_min;
    #pragma unroll 1
    for (int it = 0; it < 50; it++) {
        diff *= 0.5f;
        t = t_min + diff;
        bool mask;
        if (t < L) {
            mask = true;             // >=2 positive terms -> sum >= 1.95
        } else {
            float u1 = H - t;
            mask = (u1 >= 0.999f) ? (powf(u1, p) >= 1.0f) : false;
        }
        if (mask) t_min = t;
    }
    return t;
}

__global__ __launch_bounds__(TPB)
void entmax_bisect_kernel(const float* __restrict__ X, float* __restrict__ Y) {
    const int tid  = threadIdx.x;
    const int lane = tid & 31;
    const int wid  = tid >> 5;

    const size_t base0 = (size_t)(blockIdx.x * 2) * D;
    const size_t base1 = base0 + D;

    __shared__ float s_h0[NWARP], s_l0[NWARP];
    __shared__ float s_h1[NWARP], s_l1[NWARP];
    __shared__ float s_s0[NWARP], s_s1[NWARP];

    // ---- Load both rows (streaming), Xs = 0.5f*X (exact) ----
    const float4* Xv0 = reinterpret_cast<const float4*>(X + base0);
    const float4* Xv1 = reinterpret_cast<const float4*>(X + base1);
    float4 f0[4], f1[4];
    #pragma unroll
    for (int k = 0; k < 4; k++) f0[k] = ldcs4(Xv0 + k * TPB + tid);
    #pragma unroll
    for (int k = 0; k < 4; k++) f1[k] = ldcs4(Xv1 + k * TPB + tid);

    float xs0[VPT], xs1[VPT];
    #pragma unroll
    for (int k = 0; k < 4; k++) {
        xs0[4*k+0] = 0.5f * f0[k].x; xs0[4*k+1] = 0.5f * f0[k].y;
        xs0[4*k+2] = 0.5f * f0[k].z; xs0[4*k+3] = 0.5f * f0[k].w;
        xs1[4*k+0] = 0.5f * f1[k].x; xs1[4*k+1] = 0.5f * f1[k].y;
        xs1[4*k+2] = 0.5f * f1[k].z; xs1[4*k+3] = 0.5f * f1[k].w;
    }

    // ---- Per-thread top-2 for each row ----
    const float NEG = -3.402823466e38f;
    float hi0 = xs0[0], lo0 = NEG;
    float hi1 = xs1[0], lo1 = NEG;
    #pragma unroll
    for (int i = 1; i < VPT; i++) {
        float a = xs0[i];
        float nh = fmaxf(hi0, a);
        lo0 = fmaxf(lo0, fminf(hi0, a));
        hi0 = nh;
        float b = xs1[i];
        float mh = fmaxf(hi1, b);
        lo1 = fmaxf(lo1, fminf(hi1, b));
        hi1 = mh;
    }

    // ---- Warp butterfly top-2 (all lanes converge) ----
    #pragma unroll
    for (int off = 16; off > 0; off >>= 1) {
        float oh0 = __shfl_xor_sync(0xffffffffu, hi0, off);
        float ol0 = __shfl_xor_sync(0xffffffffu, lo0, off);
        float nh0 = fmaxf(hi0, oh0);
        lo0 = fmaxf(fmaxf(lo0, ol0), fminf(hi0, oh0));
        hi0 = nh0;
        float oh1 = __shfl_xor_sync(0xffffffffu, hi1, off);
        float ol1 = __shfl_xor_sync(0xffffffffu, lo1, off);
        float nh1 = fmaxf(hi1, oh1);
        lo1 = fmaxf(fmaxf(lo1, ol1), fminf(hi1, oh1));
        hi1 = nh1;
    }
    if (lane == 0) {
        s_h0[wid] = hi0; s_l0[wid] = lo0;
        s_h1[wid] = hi1; s_l1[wid] = lo1;
    }
    __syncthreads();

    // ---- Every thread redundantly combines 8 warps + runs bisection ----
    float H0 = s_h0[0], L0 = s_l0[0];
    float H1 = s_h1[0], L1 = s_l1[0];
    #pragma unroll
    for (int w = 1; w < NWARP; w++) {
        float oh = s_h0[w], ol = s_l0[w];
        float nh = fmaxf(H0, oh);
        L0 = fmaxf(fmaxf(L0, ol), fminf(H0, oh));
        H0 = nh;
        oh = s_h1[w]; ol = s_l1[w];
        nh = fmaxf(H1, oh);
        L1 = fmaxf(fmaxf(L1, ol), fminf(H1, oh));
        H1 = nh;
    }
    const float t0 = bisect_t(H0, L0);
    const float t1 = bisect_t(H1, L1);

    // ---- Final Z + row sums (powf on ~1-3 lanes per row) ----
    const float p = (float)(1.0 / 4095.0);
    float sum0 = 0.0f, sum1 = 0.0f;
    #pragma unroll
    for (int i = 0; i < VPT; i++) {
        float u = xs0[i] - t0;
        float z = 0.0f;
        if (u > 0.0f) z = powf(u, p);
        xs0[i] = z; sum0 += z;
        u = xs1[i] - t1;
        z = 0.0f;
        if (u > 0.0f) z = powf(u, p);
        xs1[i] = z; sum1 += z;
    }
    #pragma unroll
    for (int off = 16; off > 0; off >>= 1) {
        sum0 += __shfl_xor_sync(0xffffffffu, sum0, off);
        sum1 += __shfl_xor_sync(0xffffffffu, sum1, off);
    }
    if (lane == 0) { s_s0[wid] = sum0; s_s1[wid] = sum1; }
    __syncthreads();

    float S0 = 0.0f, S1 = 0.0f;
    #pragma unroll
    for (int w = 0; w < NWARP; w++) { S0 += s_s0[w]; S1 += s_s1[w]; }
    const float r0 = 1.0f / S0;
    const float r1 = 1.0f / S1;

    // ---- Normalize + streaming store (zeros stay exactly zero) ----
    float4* Yv0 = reinterpret_cast<float4*>(Y + base0);
    float4* Yv1 = reinterpret_cast<float4*>(Y + base1);
    #pragma unroll
    for (int k = 0; k < 4; k++) {
        float4 o;
        o.x = xs0[4*k+0] * r0; o.y = xs0[4*k+1] * r0;
        o.z = xs0[4*k+2] * r0; o.w = xs0[4*k+3] * r0;
        __stcs(Yv0 + k * TPB + tid, o);
        float4 q;
        q.x = xs1[4*k+0] * r1; q.y = xs1[4*k+1] * r1;
        q.z = xs1[4*k+2] * r1; q.w = xs1[4*k+3] * r1;
        __stcs(Yv1 + k * TPB + tid, q);
    }
}

extern "C" void kernel_launch(void* const* d_in, const int* in_sizes, int n_in,
                              void* d_out, int out_size) {
    const float* X = (const float*)d_in[0];
    float* Y = (float*)d_out;
    const int rows = in_sizes[0] / D;            // 16384
    entmax_bisect_kernel<<<rows / 2, TPB>>>(X, Y);
}

// round 3
// speedup vs baseline: 1.1550x; 1.1550x over previous
#include <cuda_runtime.h>

#define D     4096
#define TPB   512
#define VPT   8              // values per thread (2 x float4)
#define NWARP (TPB / 32)

// 50-step bisection, fp32 op-for-op identical to the reference trajectory.
// mask = (sum(Z)-1 >= 0). With p = 1/4095, u^p in [0.975, 1] for every
// positive fp32 u, so mask <=> count(Xs_j > t) >= 2, except count==1 where
// sum = powf(u1, p) can round to >= 1.0f only when u1 is within ~1e-4 of 1
// (guard at 0.999f, then evaluate the same libdevice powf the reference uses).
// Early exit: once t_min + diff rounds to t_min, mask(t_min) is true by
// invariant, so every remaining iteration leaves state unchanged and the
// final t equals t_min.
__device__ __forceinline__ float bisect_t(float Hraw, float Lraw) {
    const float H = __fmul_rn(0.5f, Hraw);   // Xs scaling, exact ordering
    const float L = __fmul_rn(0.5f, Lraw);
    const float p = (float)(1.0 / 4095.0);
    float t_min = H - 1.0f;                  // m - 1
    float t_max = H - 0.015625f;             // m - 4096^(1-1.5)
    float diff  = t_max - t_min;
    float t     = t_min;
    #pragma unroll 1
    for (int it = 0; it < 50; it++) {
        diff *= 0.5f;
        t = t_min + diff;
        if (t == t_min) break;               // converged: trajectory frozen
        bool mask;
        if (t < L) {
            mask = true;                     // >=2 positive terms -> sum >= 1.95
        } else {
            float u1 = H - t;
            mask = (u1 >= 0.999f) ? (powf(u1, p) >= 1.0f) : false;
        }
        if (mask) t_min = t;
    }
    return (t == t_min) ? t_min : t;
}

__global__ __launch_bounds__(TPB, 4)
void entmax_bisect_kernel(const float* __restrict__ X, float* __restrict__ Y) {
    const int tid  = threadIdx.x;
    const int lane = tid & 31;
    const int wid  = tid >> 5;
    const size_t base = (size_t)blockIdx.x * D;

    __shared__ float s_h[NWARP], s_l[NWARP], s_s[NWARP];
    __shared__ float s_t;

    // ---- Streaming load: 2 float4 per thread, fully coalesced ----
    const float4* Xv = reinterpret_cast<const float4*>(X + base);
    float4 f0 = __ldcs(Xv + tid);
    float4 f1 = __ldcs(Xv + TPB + tid);

    // ---- Per-thread top-2 on RAW values (x0.5 is monotone; scale later) ----
    float hi = f0.x;
    float lo = -3.402823466e38f;
    {
        float v;
        v = f0.y; lo = fmaxf(lo, fminf(hi, v)); hi = fmaxf(hi, v);
        v = f0.z; lo = fmaxf(lo, fminf(hi, v)); hi = fmaxf(hi, v);
        v = f0.w; lo = fmaxf(lo, fminf(hi, v)); hi = fmaxf(hi, v);
        v = f1.x; lo = fmaxf(lo, fminf(hi, v)); hi = fmaxf(hi, v);
        v = f1.y; lo = fmaxf(lo, fminf(hi, v)); hi = fmaxf(hi, v);
        v = f1.z; lo = fmaxf(lo, fminf(hi, v)); hi = fmaxf(hi, v);
        v = f1.w; lo = fmaxf(lo, fminf(hi, v)); hi = fmaxf(hi, v);
    }
    const float thi = hi;                    // per-thread raw max (for hot test)

    // ---- Warp butterfly top-2 ----
    #pragma unroll
    for (int off = 16; off > 0; off >>= 1) {
        float oh = __shfl_xor_sync(0xffffffffu, hi, off);
        float ol = __shfl_xor_sync(0xffffffffu, lo, off);
        float nh = fmaxf(hi, oh);
        lo = fmaxf(fmaxf(lo, ol), fminf(hi, oh));
        hi = nh;
    }
    if (lane == 0) { s_h[wid] = hi; s_l[wid] = lo; }
    __syncthreads();

    // ---- Thread 0: cross-warp combine + scalar bisection ----
    if (tid == 0) {
        float H = s_h[0], L = s_l[0];
        #pragma unroll
        for (int w = 1; w < NWARP; w++) {
            float oh = s_h[w], ol = s_l[w];
            float nh = fmaxf(H, oh);
            L = fmaxf(fmaxf(L, ol), fminf(H, oh));
            H = nh;
        }
        s_t = bisect_t(H, L);
    }
    __syncthreads();

    const float t = s_t;
    const float p = (float)(1.0 / 4095.0);

    // ---- Pass 2: only threads holding a value above t do real work ----
    // max(xs of this thread) = round(0.5*thi); monotone rounding makes the
    // thread-level test exactly equivalent to any per-element xs > t.
    const bool hot = (__fmul_rn(0.5f, thi) > t);
    float sum = 0.0f;
    if (hot) {
        float u, z;
        #define ZELEM(e) \
            u = __fmul_rn(0.5f, e) - t; \
            z = 0.0f; \
            if (u > 0.0f) { z = powf(u, p); sum += z; } \
            e = z;
        ZELEM(f0.x) ZELEM(f0.y) ZELEM(f0.z) ZELEM(f0.w)
        ZELEM(f1.x) ZELEM(f1.y) ZELEM(f1.z) ZELEM(f1.w)
        #undef ZELEM
    } else {
        f0 = make_float4(0.0f, 0.0f, 0.0f, 0.0f);
        f1 = make_float4(0.0f, 0.0f, 0.0f, 0.0f);
    }

    // ---- Row sum (mostly zeros) ----
    #pragma unroll
    for (int off = 16; off > 0; off >>= 1)
        sum += __shfl_xor_sync(0xffffffffu, sum, off);
    if (lane == 0) s_s[wid] = sum;
    __syncthreads();

    float S = 0.0f;
    #pragma unroll
    for (int w = 0; w < NWARP; w++) S += s_s[w];   // LDS broadcast, all lanes

    if (hot) {
        const float rinv = 1.0f / S;               // S > 0 always (count >= 1)
        f0.x *= rinv; f0.y *= rinv; f0.z *= rinv; f0.w *= rinv;
        f1.x *= rinv; f1.y *= rinv; f1.z *= rinv; f1.w *= rinv;
    }

    // ---- Streaming store (zeros stay exactly zero) ----
    float4* Yv = reinterpret_cast<float4*>(Y + base);
    __stcs(Yv + tid, f0);
    __stcs(Yv + TPB + tid, f1);
}

extern "C" void kernel_launch(void* const* d_in, const int* in_sizes, int n_in,
                              void* d_out, int out_size) {
    const float* X = (const float*)d_in[0];
    float* Y = (float*)d_out;
    const int rows = in_sizes[0] / D;              // 16384
    entmax_bisect_kernel<<<rows, TPB>>>(X, Y);
}

// round 5
// speedup vs baseline: 1.1929x; 1.0329x over previous
#include <cuda_runtime.h>

#define D     4096
#define TPB   256
#define NWARP (TPB / 32)

// 50-step bisection, fp32 op-for-op identical to the reference trajectory.
// mask = (sum(Z)-1 >= 0). With p = 1/4095, u^p in [0.975, 1] for every
// positive fp32 u, so mask <=> count(Xs_j > t) >= 2, except count==1 where
// sum = powf(u1,p) can round to >= 1.0f only for u1 within ~1e-4 of 1
// (guard at 0.999f, then evaluate the same libdevice powf).
// Early exit: once t = t_min + diff rounds to t_min, diff only shrinks, so
// the trajectory is frozen and the reference's final t equals t_min (== t).
__device__ __forceinline__ float bisect_t(float Hraw, float Lraw) {
    const float H = __fmul_rn(0.5f, Hraw);   // Xs = 0.5*X, exact & monotone
    const float L = __fmul_rn(0.5f, Lraw);
    const float p = (float)(1.0 / 4095.0);
    float t_min = H - 1.0f;                  // m - 1
    float t_max = H - 0.015625f;             // m - 4096^(1-1.5)
    float diff  = t_max - t_min;
    float t     = t_min;
    #pragma unroll 1
    for (int it = 0; it < 50; it++) {
        diff *= 0.5f;
        t = t_min + diff;
        if (t == t_min) break;               // frozen: final t == t_min
        bool mask;
        if (t < L) {
            mask = true;                     // >=2 positive terms -> sum >= 1.95
        } else {
            float u1 = H - t;
            mask = (u1 >= 0.999f) ? (powf(u1, p) >= 1.0f) : false;
        }
        if (mask) t_min = t;
    }
    return t;
}

__device__ __forceinline__ void load_row(float4 f[4], const float* __restrict__ Xrow,
                                         int tid) {
    const float4* Xv = reinterpret_cast<const float4*>(Xrow);
    #pragma unroll
    for (int k = 0; k < 4; k++) f[k] = Xv[k * TPB + tid];
}

__device__ __forceinline__ void process_row(float4 f[4], float* __restrict__ Yrow,
                                            int tid, int lane, int wid,
                                            float* s_h, float* s_l, float* s_s,
                                            float* s_t) {
    // ---- Per-thread top-2 on RAW values (x0.5 monotone; scaled in bisect) ----
    float hi = f[0].x;
    float lo = -3.402823466e38f;
    {
        float v;
        v = f[0].y; lo = fmaxf(lo, fminf(hi, v)); hi = fmaxf(hi, v);
        v = f[0].z; lo = fmaxf(lo, fminf(hi, v)); hi = fmaxf(hi, v);
        v = f[0].w; lo = fmaxf(lo, fminf(hi, v)); hi = fmaxf(hi, v);
        #pragma unroll
        for (int k = 1; k < 4; k++) {
            v = f[k].x; lo = fmaxf(lo, fminf(hi, v)); hi = fmaxf(hi, v);
            v = f[k].y; lo = fmaxf(lo, fminf(hi, v)); hi = fmaxf(hi, v);
            v = f[k].z; lo = fmaxf(lo, fminf(hi, v)); hi = fmaxf(hi, v);
            v = f[k].w; lo = fmaxf(lo, fminf(hi, v)); hi = fmaxf(hi, v);
        }
    }
    const float thi = hi;                    // per-thread raw max

    // ---- Warp butterfly top-2 ----
    #pragma unroll
    for (int off = 16; off > 0; off >>= 1) {
        float oh = __shfl_xor_sync(0xffffffffu, hi, off);
        float ol = __shfl_xor_sync(0xffffffffu, lo, off);
        float nh = fmaxf(hi, oh);
        lo = fmaxf(fmaxf(lo, ol), fminf(hi, oh));
        hi = nh;
    }
    if (lane == 0) { s_h[wid] = hi; s_l[wid] = lo; }
    __syncthreads();                         // b1

    if (tid == 0) {
        float H = s_h[0], L = s_l[0];
        #pragma unroll
        for (int w = 1; w < NWARP; w++) {
            float oh = s_h[w], ol = s_l[w];
            float nh = fmaxf(H, oh);
            L = fmaxf(fmaxf(L, ol), fminf(H, oh));
            H = nh;
        }
        *s_t = bisect_t(H, L);
    }
    __syncthreads();                         // b2

    const float t = *s_t;
    const float p = (float)(1.0 / 4095.0);

    // ---- Pass 2: only threads holding a value above t do real work ----
    const bool hot = (__fmul_rn(0.5f, thi) > t);
    float sum = 0.0f;
    if (hot) {
        float u, z;
        #define ZELEM(e) \
            u = __fmul_rn(0.5f, e) - t; \
            z = 0.0f; \
            if (u > 0.0f) { z = powf(u, p); sum += z; } \
            e = z;
        ZELEM(f[0].x) ZELEM(f[0].y) ZELEM(f[0].z) ZELEM(f[0].w)
        ZELEM(f[1].x) ZELEM(f[1].y) ZELEM(f[1].z) ZELEM(f[1].w)
        ZELEM(f[2].x) ZELEM(f[2].y) ZELEM(f[2].z) ZELEM(f[2].w)
        ZELEM(f[3].x) ZELEM(f[3].y) ZELEM(f[3].z) ZELEM(f[3].w)
        #undef ZELEM
    } else {
        #pragma unroll
        for (int k = 0; k < 4; k++) f[k] = make_float4(0.0f, 0.0f, 0.0f, 0.0f);
    }

    #pragma unroll
    for (int off = 16; off > 0; off >>= 1)
        sum += __shfl_xor_sync(0xffffffffu, sum, off);
    if (lane == 0) s_s[wid] = sum;
    __syncthreads();                         // b3

    float S = 0.0f;
    #pragma unroll
    for (int w = 0; w < NWARP; w++) S += s_s[w];

    if (hot) {
        const float rinv = 1.0f / S;         // S > 0 always
        #pragma unroll
        for (int k = 0; k < 4; k++) {
            f[k].x *= rinv; f[k].y *= rinv; f[k].z *= rinv; f[k].w *= rinv;
        }
    }

    float4* Yv = reinterpret_cast<float4*>(Yrow);
    #pragma unroll
    for (int k = 0; k < 4; k++) __stcs(Yv + k * TPB + tid, f[k]);
}

__global__ __launch_bounds__(TPB, 4)
void entmax_bisect_kernel(const float* __restrict__ X, float* __restrict__ Y,
                          int rows) {
    __shared__ float s_h[NWARP], s_l[NWARP], s_s[NWARP];
    __shared__ float s_t;

    const int tid  = threadIdx.x;
    const int lane = tid & 31;
    const int wid  = tid >> 5;
    const int stride = gridDim.x;

    int r = blockIdx.x;
    if (r >= rows) return;

    float4 A[4], B[4];
    load_row(A, X + (size_t)r * D, tid);

    // Software pipeline: issue next row's loads before processing current row,
    // so DRAM traffic covers the reduce/bisect/epilogue bubble.
    while (true) {
        int rn = r + stride;
        bool more = (rn < rows);
        if (more) load_row(B, X + (size_t)rn * D, tid);
        process_row(A, Y + (size_t)r * D, tid, lane, wid, s_h, s_l, s_s, &s_t);
        if (!more) break;
        r = rn;

        rn = r + stride;
        more = (rn < rows);
        if (more) load_row(A, X + (size_t)rn * D, tid);
        process_row(B, Y + (size_t)r * D, tid, lane, wid, s_h, s_l, s_s, &s_t);
        if (!more) break;
        r = rn;
    }
}

extern "C" void kernel_launch(void* const* d_in, const int* in_sizes, int n_in,
                              void* d_out, int out_size) {
    const float* X = (const float*)d_in[0];
    float* Y = (float*)d_out;
    const int rows = in_sizes[0] / D;              // 16384
    int grid = 4 * 148;                            // persistent: 4 CTAs/SM
    if (grid > rows) grid = rows;
    entmax_bisect_kernel<<<grid, TPB>>>(X, Y, rows);
}

// round 6
// speedup vs baseline: 1.3930x; 1.1677x over previous
#include <cuda_runtime.h>

#define D     4096
#define TPB   256
#define NWARP (TPB / 32)

// Forced re-read (asm volatile so the compiler cannot CSE it with the pass-1
// loads and keep 16 registers alive across barriers).
__device__ __forceinline__ float4 reload4(const float4* p) {
    float4 v;
    asm volatile("ld.global.ca.v4.f32 {%0,%1,%2,%3}, [%4];"
                 : "=f"(v.x), "=f"(v.y), "=f"(v.z), "=f"(v.w)
                 : "l"(p));
    return v;
}

// 50-step bisection, fp32 op-for-op identical to the reference trajectory.
// mask = (sum(Z)-1 >= 0). With p = 1/4095, u^p in [0.975, 1] for every
// positive fp32 u, so mask <=> count(Xs_j > t) >= 2, except count==1 where
// sum = powf(u1,p) can round to >= 1.0f only for u1 within ~1e-4 of 1
// (guard at 0.999f, then evaluate the same libdevice powf).
// Early exit: once t = t_min + diff rounds to t_min, rounding monotonicity
// freezes the trajectory (smaller diff also rounds to t_min) and the
// reference's final t equals t_min.
__device__ __forceinline__ float bisect_t(float Hraw, float Lraw) {
    const float H = __fmul_rn(0.5f, Hraw);   // Xs = 0.5*X, exact & monotone
    const float L = __fmul_rn(0.5f, Lraw);
    const float p = (float)(1.0 / 4095.0);
    float t_min = H - 1.0f;                  // m - 1
    float t_max = H - 0.015625f;             // m - 4096^(1-1.5)
    float diff  = t_max - t_min;
    float t     = t_min;
    #pragma unroll 1
    for (int it = 0; it < 50; it++) {
        diff *= 0.5f;
        t = t_min + diff;
        if (t == t_min) break;               // frozen: final t == t_min
        bool mask;
        if (t < L) {
            mask = true;                     // >=2 positive terms -> sum >= 1.95
        } else {
            float u1 = H - t;
            mask = (u1 >= 0.999f) ? (powf(u1, p) >= 1.0f) : false;
        }
        if (mask) t_min = t;
    }
    return t;
}

__global__ __launch_bounds__(TPB, 8)
void entmax_bisect_kernel(const float* __restrict__ X, float* __restrict__ Y) {
    const int tid  = threadIdx.x;
    const int lane = tid & 31;
    const int wid  = tid >> 5;
    const size_t base = (size_t)blockIdx.x * D;

    __shared__ float s_h[NWARP], s_l[NWARP], s_s[NWARP];
    __shared__ float s_t;

    const float4* Xv = reinterpret_cast<const float4*>(X + base);
    float4*       Yv = reinterpret_cast<float4*>(Y + base);

    // ---- Pass 1: load 16 values, fold into top-2, DROP the values ----
    float hi, lo = -3.402823466e38f;
    {
        float4 f0 = Xv[tid];
        float4 f1 = Xv[TPB + tid];
        float4 f2 = Xv[2 * TPB + tid];
        float4 f3 = Xv[3 * TPB + tid];
        float v;
        hi = f0.x;
        v = f0.y; lo = fmaxf(lo, fminf(hi, v)); hi = fmaxf(hi, v);
        v = f0.z; lo = fmaxf(lo, fminf(hi, v)); hi = fmaxf(hi, v);
        v = f0.w; lo = fmaxf(lo, fminf(hi, v)); hi = fmaxf(hi, v);
        v = f1.x; lo = fmaxf(lo, fminf(hi, v)); hi = fmaxf(hi, v);
        v = f1.y; lo = fmaxf(lo, fminf(hi, v)); hi = fmaxf(hi, v);
        v = f1.z; lo = fmaxf(lo, fminf(hi, v)); hi = fmaxf(hi, v);
        v = f1.w; lo = fmaxf(lo, fminf(hi, v)); hi = fmaxf(hi, v);
        v = f2.x; lo = fmaxf(lo, fminf(hi, v)); hi = fmaxf(hi, v);
        v = f2.y; lo = fmaxf(lo, fminf(hi, v)); hi = fmaxf(hi, v);
        v = f2.z; lo = fmaxf(lo, fminf(hi, v)); hi = fmaxf(hi, v);
        v = f2.w; lo = fmaxf(lo, fminf(hi, v)); hi = fmaxf(hi, v);
        v = f3.x; lo = fmaxf(lo, fminf(hi, v)); hi = fmaxf(hi, v);
        v = f3.y; lo = fmaxf(lo, fminf(hi, v)); hi = fmaxf(hi, v);
        v = f3.z; lo = fmaxf(lo, fminf(hi, v)); hi = fmaxf(hi, v);
        v = f3.w; lo = fmaxf(lo, fminf(hi, v)); hi = fmaxf(hi, v);
    }
    const float thi = hi;                    // per-thread raw max

    // ---- Warp butterfly top-2 ----
    #pragma unroll
    for (int off = 16; off > 0; off >>= 1) {
        float oh = __shfl_xor_sync(0xffffffffu, hi, off);
        float ol = __shfl_xor_sync(0xffffffffu, lo, off);
        float nh = fmaxf(hi, oh);
        lo = fmaxf(fmaxf(lo, ol), fminf(hi, oh));
        hi = nh;
    }
    if (lane == 0) { s_h[wid] = hi; s_l[wid] = lo; }
    __syncthreads();                                      // b1

    // ---- All threads: combine 8 warps' top-2 (cheap, 16 LDS) ----
    float Hb = s_h[0], Lb = s_l[0];
    #pragma unroll
    for (int w = 1; w < NWARP; w++) {
        float oh = s_h[w], ol = s_l[w];
        float nh = fmaxf(Hb, oh);
        Lb = fmaxf(fmaxf(Lb, ol), fminf(Hb, oh));
        Hb = nh;
    }

    // ---- Sure-cold test: t_final >= min(L_s, H_s - 0.015625) - 2*diff_final.
    // Threads whose max Xs is below that (with fat margin) produce only zeros
    // and can store NOW, overlapping the bisection bubble below. ----
    const float Hs   = __fmul_rn(0.5f, Hb);
    const float Ls   = __fmul_rn(0.5f, Lb);
    const float thr  = fminf(Ls, Hs - 0.015625f) - 2e-5f;
    const float myXs = __fmul_rn(0.5f, thi);
    const bool sure_cold = (myXs < thr);

    const float4 zero4 = make_float4(0.0f, 0.0f, 0.0f, 0.0f);
    if (sure_cold) {
        __stcs(Yv + tid,           zero4);
        __stcs(Yv + TPB + tid,     zero4);
        __stcs(Yv + 2 * TPB + tid, zero4);
        __stcs(Yv + 3 * TPB + tid, zero4);
    }

    // ---- Thread 0: scalar bisection (zero-stores above already in flight) ----
    if (tid == 0) s_t = bisect_t(Hb, Lb);
    __syncthreads();                                      // b2

    const float t = s_t;
    const float p = (float)(1.0 / 4095.0);
    const bool hot = (!sure_cold) && (myXs > t);

    // ---- Pass 2 (hot threads only, ~1-3 per row): re-read (L1 hit), sum z ----
    float sum = 0.0f;
    if (hot) {
        #pragma unroll
        for (int k = 0; k < 4; k++) {
            float4 g = reload4(Xv + k * TPB + tid);
            float u;
            u = __fmul_rn(0.5f, g.x) - t; if (u > 0.0f) sum += powf(u, p);
            u = __fmul_rn(0.5f, g.y) - t; if (u > 0.0f) sum += powf(u, p);
            u = __fmul_rn(0.5f, g.z) - t; if (u > 0.0f) sum += powf(u, p);
            u = __fmul_rn(0.5f, g.w) - t; if (u > 0.0f) sum += powf(u, p);
        }
    }
    #pragma unroll
    for (int off = 16; off > 0; off >>= 1)
        sum += __shfl_xor_sync(0xffffffffu, sum, off);
    if (lane == 0) s_s[wid] = sum;
    __syncthreads();                                      // b3

    float S = 0.0f;
    #pragma unroll
    for (int w = 0; w < NWARP; w++) S += s_s[w];

    // ---- Epilogue: hot threads recompute+normalize+store; unsure-cold store 0 ----
    if (hot) {
        const float rinv = 1.0f / S;                      // S > 0 always
        #pragma unroll
        for (int k = 0; k < 4; k++) {
            float4 g = reload4(Xv + k * TPB + tid);       // L1 hit
            float4 o = zero4;
            float u;
            u = __fmul_rn(0.5f, g.x) - t; if (u > 0.0f) o.x = powf(u, p) * rinv;
            u = __fmul_rn(0.5f, g.y) - t; if (u > 0.0f) o.y = powf(u, p) * rinv;
            u = __fmul_rn(0.5f, g.z) - t; if (u > 0.0f) o.z = powf(u, p) * rinv;
            u = __fmul_rn(0.5f, g.w) - t; if (u > 0.0f) o.w = powf(u, p) * rinv;
            __stcs(Yv + k * TPB + tid, o);
        }
    } else if (!sure_cold) {
        __stcs(Yv + tid,           zero4);
        __stcs(Yv + TPB + tid,     zero4);
        __stcs(Yv + 2 * TPB + tid, zero4);
        __stcs(Yv + 3 * TPB + tid, zero4);
    }
}

extern "C" void kernel_launch(void* const* d_in, const int* in_sizes, int n_in,
                              void* d_out, int out_size) {
    const float* X = (const float*)d_in[0];
    float* Y = (float*)d_out;
    const int rows = in_sizes[0] / D;                     // 16384
    entmax_bisect_kernel<<<rows, TPB>>>(X, Y);
}